// round 16
// baseline (speedup 1.0000x reference)
#include <cuda_runtime.h>
#include <cuda_bf16.h>
#include <cstdint>

// ============================================================================
// AdditiveAttention: out = softmax_mask( sum_h tanh(Q@Wq + K@Wk) * wv ) @ V
// B=16, Q=128, K=128, D=512, H=512
//  prep       : W^T fp32->bf16 hi/lo split
//  bf16_gemm  : Qp/Kp = A@W, mma m16n8k16 bf16 3-term split; A split in regs
//  score_av   : persistent 296 x 512thr (2 blocks/SM), two-phase queue:
//               [0,1024)  score tasks (b-major, 64/batch: qt x hq x kh)
//               [1024,1280) AV tasks (b, q-octet) gated on per-batch counters
// ============================================================================

#define BDIM 16
#define QDIM 128
#define KDIM 128
#define DDIM 512
#define HDIM 512
#define NT_SCORE 1024
#define NT_ALL   1280
#define NBLOCKS  296

__device__ float g_Qp[BDIM * QDIM * HDIM];     // 4 MB
__device__ float g_Kp[BDIM * KDIM * HDIM];     // 4 MB
__device__ float g_S[4][BDIM][QDIM][KDIM];     // partial scores, 4 MB
__device__ int   g_counter;
__device__ int   g_done;
__device__ int   g_bdone[BDIM];                // completed score tasks per batch

__device__ unsigned short g_Bth[2][512 * 512];   // W^T : [n][k]
__device__ unsigned short g_Btl[2][512 * 512];

__device__ __forceinline__ float tanh_fast(float x) {
    float y;
    asm("tanh.approx.f32 %0, %1;" : "=f"(y) : "f"(x));
    return y;
}
__device__ __forceinline__ void bf16_split(float x, unsigned short& hi, unsigned short& lo) {
    __nv_bfloat16 h = __float2bfloat16_rn(x);
    __nv_bfloat16 l = __float2bfloat16_rn(x - __bfloat162float(h));
    hi = __bfloat16_as_ushort(h);
    lo = __bfloat16_as_ushort(l);
}
__device__ __forceinline__ void ldsm_x4(uint32_t* r, uint32_t addr) {
    asm volatile("ldmatrix.sync.aligned.m8n8.x4.shared.b16 {%0,%1,%2,%3}, [%4];"
        : "=r"(r[0]), "=r"(r[1]), "=r"(r[2]), "=r"(r[3]) : "r"(addr));
}
__device__ __forceinline__ void mma_bf16(float* c, const uint32_t* a, const uint32_t* b) {
    asm volatile("mma.sync.aligned.m16n8k16.row.col.f32.bf16.bf16.f32 "
        "{%0,%1,%2,%3}, {%4,%5,%6,%7}, {%8,%9}, {%0,%1,%2,%3};"
        : "+f"(c[0]), "+f"(c[1]), "+f"(c[2]), "+f"(c[3])
        : "r"(a[0]), "r"(a[1]), "r"(a[2]), "r"(a[3]), "r"(b[0]), "r"(b[1]));
}

// ----------------------------------------------------------------------------
// prep: W^T split. grid (256, 2) x 256 threads; block = one 32x32 tile.
// ----------------------------------------------------------------------------
__global__ void prep(const float* __restrict__ Wq, const float* __restrict__ Wk)
{
    __shared__ float tile[32][33];
    const int z = blockIdx.y;
    const float* W = z ? Wk : Wq;
    const int wb = blockIdx.x;
    const int n0 = (wb & 15) * 32;
    const int k0 = (wb >> 4) * 32;
    const int tid = threadIdx.x;
    const int tx = tid & 31;
    const int ty = tid >> 5;
#pragma unroll
    for (int i = 0; i < 4; i++) {
        const int r = ty + i * 8;
        tile[r][tx] = W[(k0 + r) * 512 + n0 + tx];
    }
    __syncthreads();
#pragma unroll
    for (int i = 0; i < 4; i++) {
        const int r = ty + i * 8;
        unsigned short hi, lo;
        bf16_split(tile[tx][r], hi, lo);
        g_Bth[z][(n0 + r) * 512 + k0 + tx] = hi;
        g_Btl[z][(n0 + r) * 512 + k0 + tx] = lo;
    }
}

// ----------------------------------------------------------------------------
// bf16_gemm (unchanged from R15)
// ----------------------------------------------------------------------------
#define KC 32
#define AST 40

__global__ __launch_bounds__(256, 1) void bf16_gemm(
    const float* __restrict__ Aq, const float* __restrict__ Ak)
{
    const int z  = blockIdx.z;
    const int m0 = blockIdx.y * 128;
    const int n0 = blockIdx.x * 128;

    const float* Af = z ? Ak : Aq;
    const unsigned short* Bh = g_Bth[z];
    const unsigned short* Bl = g_Btl[z];
    float* C = z ? g_Kp : g_Qp;

    __shared__ __align__(16) unsigned short sAh[128 * AST];
    __shared__ __align__(16) unsigned short sAl[128 * AST];
    __shared__ __align__(16) unsigned short sBh[128 * AST];
    __shared__ __align__(16) unsigned short sBl[128 * AST];

    const int tid  = threadIdx.x;
    const int lane = tid & 31;
    const int wid  = tid >> 5;
    const int warp_m = wid & 3;
    const int warp_n = wid >> 2;

    const int lr = tid >> 1;
    const int lc = (tid & 1) * 16;

    const int grp = lane >> 3, l8 = lane & 7;
    const uint32_t sAh_b = (uint32_t)__cvta_generic_to_shared(sAh);
    const uint32_t sAl_b = (uint32_t)__cvta_generic_to_shared(sAl);
    const uint32_t sBh_b = (uint32_t)__cvta_generic_to_shared(sBh);
    const uint32_t sBl_b = (uint32_t)__cvta_generic_to_shared(sBl);
    const uint32_t aoff = ((warp_m * 32 + (grp & 1) * 8 + l8) * AST + (grp >> 1) * 8) * 2;
    const uint32_t boff = ((warp_n * 64 + (grp >> 1) * 8 + l8) * AST + (grp & 1) * 8) * 2;

    float acc[2][8][4];
#pragma unroll
    for (int mt = 0; mt < 2; mt++)
#pragma unroll
        for (int nt = 0; nt < 8; nt++)
#pragma unroll
            for (int i = 0; i < 4; i++) acc[mt][nt][i] = 0.0f;

    const int ga0 = (m0 + lr) * 512 + lc;
    const int gb0 = (n0 + lr) * 512 + lc;

    float fa[16];
    uint4 rbh0, rbh1, rbl0, rbl1;
#pragma unroll
    for (int i = 0; i < 4; i++)
        *(float4*)&fa[i * 4] = *(const float4*)&Af[ga0 + i * 4];
    rbh0 = *(const uint4*)&Bh[gb0];     rbh1 = *(const uint4*)&Bh[gb0 + 8];
    rbl0 = *(const uint4*)&Bl[gb0];     rbl1 = *(const uint4*)&Bl[gb0 + 8];

    const int NKC = 512 / KC;
    for (int it = 0; it < NKC; ++it) {
        {
            unsigned short ha[16], la[16];
#pragma unroll
            for (int i = 0; i < 16; i++) bf16_split(fa[i], ha[i], la[i]);
            *(uint4*)&sAh[lr * AST + lc]     = *(uint4*)&ha[0];
            *(uint4*)&sAh[lr * AST + lc + 8] = *(uint4*)&ha[8];
            *(uint4*)&sAl[lr * AST + lc]     = *(uint4*)&la[0];
            *(uint4*)&sAl[lr * AST + lc + 8] = *(uint4*)&la[8];
        }
        *(uint4*)&sBh[lr * AST + lc]     = rbh0;
        *(uint4*)&sBh[lr * AST + lc + 8] = rbh1;
        *(uint4*)&sBl[lr * AST + lc]     = rbl0;
        *(uint4*)&sBl[lr * AST + lc + 8] = rbl1;
        __syncthreads();

        if (it + 1 < NKC) {
            const int ga = ga0 + (it + 1) * KC;
            const int gb = gb0 + (it + 1) * KC;
#pragma unroll
            for (int i = 0; i < 4; i++)
                *(float4*)&fa[i * 4] = *(const float4*)&Af[ga + i * 4];
            rbh0 = *(const uint4*)&Bh[gb];     rbh1 = *(const uint4*)&Bh[gb + 8];
            rbl0 = *(const uint4*)&Bl[gb];     rbl1 = *(const uint4*)&Bl[gb + 8];
        }

#pragma unroll
        for (int ks = 0; ks < KC; ks += 16) {
            uint32_t ah[2][4], al[2][4], bh[4][4], bl[4][4];
#pragma unroll
            for (int mt = 0; mt < 2; mt++) {
                ldsm_x4(ah[mt], sAh_b + aoff + mt * (16 * AST * 2) + ks * 2);
                ldsm_x4(al[mt], sAl_b + aoff + mt * (16 * AST * 2) + ks * 2);
            }
#pragma unroll
            for (int j = 0; j < 4; j++) {
                ldsm_x4(bh[j], sBh_b + boff + j * (16 * AST * 2) + ks * 2);
                ldsm_x4(bl[j], sBl_b + boff + j * (16 * AST * 2) + ks * 2);
            }
#pragma unroll
            for (int mt = 0; mt < 2; mt++)
#pragma unroll
                for (int nt = 0; nt < 8; nt++) {
                    const uint32_t* ph = &bh[nt >> 1][(nt & 1) * 2];
                    const uint32_t* pl = &bl[nt >> 1][(nt & 1) * 2];
                    mma_bf16(acc[mt][nt], ah[mt], ph);
                    mma_bf16(acc[mt][nt], ah[mt], pl);
                    mma_bf16(acc[mt][nt], al[mt], ph);
                }
        }
        __syncthreads();
    }

    const int g = lane >> 2, t = lane & 3;
#pragma unroll
    for (int mt = 0; mt < 2; mt++) {
        const int row = m0 + warp_m * 32 + mt * 16 + g;
#pragma unroll
        for (int nt = 0; nt < 8; nt++) {
            const int col = n0 + warp_n * 64 + nt * 8 + t * 2;
            *(float2*)&C[row * 512 + col]       = make_float2(acc[mt][nt][0], acc[mt][nt][1]);
            *(float2*)&C[(row + 8) * 512 + col] = make_float2(acc[mt][nt][2], acc[mt][nt][3]);
        }
    }
}

// ----------------------------------------------------------------------------
// score_av: two-phase persistent kernel.
// Phase 1 (t < 1024): score task. b = t>>6; rem = t&63: qt = rem>>3,
//   hq = (rem>>1)&3, kh = rem&1. Writes S[hq][b][qt*16+w][kh*64+...],
//   then increments g_bdone[b] (skipped tasks increment too).
// Phase 2 (t >= 1024): AV task a = t-1024: b = a>>4, qo = a&15. Spins until
//   g_bdone[b]==64, then softmax (warp-pair merge) + AV (MLP-4).
// ----------------------------------------------------------------------------
#define HC 64
#define KS_STRIDE 68
#define POOL_FLOATS (64 * KS_STRIDE + 16 * KS_STRIDE + HDIM)   // 23.8KB

__global__ __launch_bounds__(512, 2) void score_av(
    const int* __restrict__ valid_lens,
    const float* __restrict__ wv,
    const float* __restrict__ values,
    float* __restrict__ out)
{
    const int tid = threadIdx.x;
    const int tk  = tid & 31;
    const int w   = tid >> 5;

    __shared__ __align__(16) float pool[POOL_FLOATS];
    float (*Ks)[KS_STRIDE] = (float(*)[KS_STRIDE])&pool[0];
    float (*Qs)[KS_STRIDE] = (float(*)[KS_STRIDE])&pool[64 * KS_STRIDE];
    float* wvs = &pool[80 * KS_STRIDE];
    float (*attnT)[12] = (float(*)[12])&pool[0];        // aliases Ks in AV phase
    __shared__ float pm[8][2], ps[8][2];
    __shared__ int s_task;

    if (tid < 128)
        *(float4*)&wvs[tid * 4] = *(const float4*)&wv[tid * 4];

    const int kq_row = tid >> 4;
    const int kq_c4  = tid & 15;
    const int q_row  = tid >> 4;
    const int q_c4   = tid & 15;

    for (;;) {
        if (tid == 0) s_task = atomicAdd(&g_counter, 1);
        __syncthreads();
        const int t = s_task;
        if (t >= NT_ALL) break;

        if (t < NT_SCORE) {
            // ================= Phase 1: score task =================
            const int b   = t >> 6;
            const int rem = t & 63;
            const int qt  = rem >> 3;
            const int hq  = (rem >> 1) & 3;
            const int kh  = rem & 1;
            const int vlen = valid_lens[b];
            const int kmax = min(KDIM, (vlen + 31) & ~31);
            const int kbase = kh * 64;

            if (kbase >= kmax) {
                __syncthreads();
                if (tid == 0) atomicAdd(&g_bdone[b], 1);   // trivially complete
                continue;
            }

            const bool act1 = (kbase + 32 < vlen);
            const int hbase = hq * (HDIM / 4);

            const float* Qp = g_Qp + (b * QDIM + qt * 16) * HDIM;
            const float* Kp = g_Kp + (b * KDIM + kbase) * HDIM;

            float4 pk[2];
            float4 pq;

            const int krows = kmax - kbase;
#pragma unroll
            for (int i = 0; i < 2; i++)
                if (kq_row + 32 * i < krows)
                    pk[i] = *(const float4*)&Kp[(kq_row + 32 * i) * HDIM + hbase + kq_c4 * 4];
            if (tid < 256)
                pq = *(const float4*)&Qp[q_row * HDIM + hbase + q_c4 * 4];

#pragma unroll
            for (int i = 0; i < 2; i++)
                if (kq_row + 32 * i < krows)
                    *(float4*)&Ks[kq_row + 32 * i][kq_c4 * 4] = pk[i];
            if (tid < 256)
                *(float4*)&Qs[q_row][q_c4 * 4] = pq;
            __syncthreads();

            float s0 = 0.0f, s1 = 0.0f;

            const int NCH = (HDIM / 4) / HC;   // 2
            for (int hc = 0; hc < NCH; ++hc) {
                const int h0 = hbase + hc * HC;
                if (hc + 1 < NCH) {
                    const int hn = h0 + HC;
#pragma unroll
                    for (int i = 0; i < 2; i++)
                        if (kq_row + 32 * i < krows)
                            pk[i] = *(const float4*)&Kp[(kq_row + 32 * i) * HDIM + hn + kq_c4 * 4];
                    if (tid < 256)
                        pq = *(const float4*)&Qp[q_row * HDIM + hn + q_c4 * 4];
                }

#pragma unroll
                for (int h4 = 0; h4 < HC / 4; ++h4) {
                    const float4 w4 = *(const float4*)&wvs[h0 + h4 * 4];
                    const float4 qa = *(const float4*)&Qs[w][h4 * 4];
                    {
                        const float4 kv = *(const float4*)&Ks[tk][h4 * 4];
                        s0 = fmaf(tanh_fast(qa.x + kv.x), w4.x, s0);
                        s0 = fmaf(tanh_fast(qa.y + kv.y), w4.y, s0);
                        s0 = fmaf(tanh_fast(qa.z + kv.z), w4.z, s0);
                        s0 = fmaf(tanh_fast(qa.w + kv.w), w4.w, s0);
                    }
                    if (act1) {
                        const float4 kv = *(const float4*)&Ks[tk + 32][h4 * 4];
                        s1 = fmaf(tanh_fast(qa.x + kv.x), w4.x, s1);
                        s1 = fmaf(tanh_fast(qa.y + kv.y), w4.y, s1);
                        s1 = fmaf(tanh_fast(qa.z + kv.z), w4.z, s1);
                        s1 = fmaf(tanh_fast(qa.w + kv.w), w4.w, s1);
                    }
                }
                __syncthreads();
                if (hc + 1 < NCH) {
#pragma unroll
                    for (int i = 0; i < 2; i++)
                        if (kq_row + 32 * i < krows)
                            *(float4*)&Ks[kq_row + 32 * i][kq_c4 * 4] = pk[i];
                    if (tid < 256)
                        *(float4*)&Qs[q_row][q_c4 * 4] = pq;
                    __syncthreads();
                }
            }

            float* Sp = &g_S[hq][b][qt * 16 + w][0];
            Sp[kbase + tk] = s0;
            if (act1) Sp[kbase + tk + 32] = s1;

            // publish completion: all threads fence, then one increments
            __threadfence();
            __syncthreads();
            if (tid == 0) atomicAdd(&g_bdone[b], 1);
        } else {
            // ================= Phase 2: AV task =================
            const int a  = t - NT_SCORE;
            const int b  = a >> 4;
            const int qo = a & 15;

            // wait for this batch's 64 score tasks
            if (tid == 0) {
                while (atomicAdd(&g_bdone[b], 0) < 64) { }
            }
            __syncthreads();
            __threadfence();

            const int vlen = valid_lens[b];
            const int kmax = min(KDIM, (vlen + 31) & ~31);

            const int row = w >> 1;
            const int w2  = w & 1;
            const int qrow = qo * 8 + row;
            const float* S0 = &g_S[0][b][qrow][0];
            const float* S1 = &g_S[1][b][qrow][0];
            const float* S2 = &g_S[2][b][qrow][0];
            const float* S3 = &g_S[3][b][qrow][0];

            const int k0 = tk + 64 * w2;
            const int k1 = tk + 32 + 64 * w2;
            float s0 = (k0 < kmax)
                ? ((__ldcg(&S0[k0]) + __ldcg(&S1[k0])) + (__ldcg(&S2[k0]) + __ldcg(&S3[k0])))
                : -1e6f;
            float s1 = (k1 < kmax)
                ? ((__ldcg(&S0[k1]) + __ldcg(&S1[k1])) + (__ldcg(&S2[k1]) + __ldcg(&S3[k1])))
                : -1e6f;
            if (k0 >= vlen) s0 = -1e6f;
            if (k1 >= vlen) s1 = -1e6f;

            float m = fmaxf(s0, s1);
#pragma unroll
            for (int off = 16; off > 0; off >>= 1)
                m = fmaxf(m, __shfl_xor_sync(0xFFFFFFFFu, m, off));
            const float e0 = __expf(s0 - m), e1 = __expf(s1 - m);
            float sum = e0 + e1;
#pragma unroll
            for (int off = 16; off > 0; off >>= 1)
                sum += __shfl_xor_sync(0xFFFFFFFFu, sum, off);
            if (tk == 0) { pm[row][w2] = m; ps[row][w2] = sum; }
            __syncthreads();

            const float m0p = pm[row][0], m1p = pm[row][1];
            const float mg = fmaxf(m0p, m1p);
            const float sg = ps[row][0] * __expf(m0p - mg) + ps[row][1] * __expf(m1p - mg);
            const float rs = __expf(pm[row][w2] - mg) / sg;
            attnT[k0][row] = e0 * rs;
            attnT[k1][row] = e1 * rs;
            __syncthreads();

            const int d = tid;
            const float* Vb = values + b * KDIM * DDIM + d;
            float acc[8];
#pragma unroll
            for (int q = 0; q < 8; q++) acc[q] = 0.0f;

            for (int k = 0; k < kmax; k += 4) {
                const float v0 = Vb[(k + 0) * DDIM];
                const float v1 = Vb[(k + 1) * DDIM];
                const float v2 = Vb[(k + 2) * DDIM];
                const float v3 = Vb[(k + 3) * DDIM];
                float a0[8], a1[8], a2[8], a3[8];
                *(float4*)&a0[0] = *(const float4*)&attnT[k + 0][0];
                *(float4*)&a0[4] = *(const float4*)&attnT[k + 0][4];
                *(float4*)&a1[0] = *(const float4*)&attnT[k + 1][0];
                *(float4*)&a1[4] = *(const float4*)&attnT[k + 1][4];
                *(float4*)&a2[0] = *(const float4*)&attnT[k + 2][0];
                *(float4*)&a2[4] = *(const float4*)&attnT[k + 2][4];
                *(float4*)&a3[0] = *(const float4*)&attnT[k + 3][0];
                *(float4*)&a3[4] = *(const float4*)&attnT[k + 3][4];
#pragma unroll
                for (int q = 0; q < 8; q++) {
                    acc[q] = fmaf(a0[q], v0, acc[q]);
                    acc[q] = fmaf(a1[q], v1, acc[q]);
                    acc[q] = fmaf(a2[q], v2, acc[q]);
                    acc[q] = fmaf(a3[q], v3, acc[q]);
                }
            }

            float* Ob = out + (b * QDIM + qo * 8) * DDIM + d;
#pragma unroll
            for (int q = 0; q < 8; q++)
                Ob[q * DDIM] = acc[q];
            __syncthreads();   // attnT (pool) reuse safety before next task
        }
    }

    // self-reset queue + per-batch counters for next graph replay
    if (tid == 0) {
        __threadfence();
        const int d = atomicAdd(&g_done, 1);
        if (d == NBLOCKS - 1) {
            g_counter = 0;
            g_done = 0;
#pragma unroll
            for (int i = 0; i < BDIM; i++) g_bdone[i] = 0;
        }
    }
}

// ----------------------------------------------------------------------------
extern "C" void kernel_launch(void* const* d_in, const int* in_sizes, int n_in,
                              void* d_out, int out_size)
{
    const float* queries    = (const float*)d_in[0];
    const float* keys       = (const float*)d_in[1];
    const float* values     = (const float*)d_in[2];
    const int*   valid_lens = (const int*)d_in[3];
    const float* Wq         = (const float*)d_in[4];
    const float* Wk         = (const float*)d_in[5];
    const float* wv         = (const float*)d_in[6];
    float* out = (float*)d_out;

    prep<<<dim3(256, 2), 256>>>(Wq, Wk);
    bf16_gemm<<<dim3(4, 16, 2), 256>>>(queries, keys);
    score_av<<<NBLOCKS, 512>>>(valid_lens, wv, values, out);
}